// round 1
// baseline (speedup 1.0000x reference)
#include <cuda_runtime.h>
#include <math.h>

#define NN 50000
#define EE 800000
#define INC 128
#define HIDC 64
#define NHEADS 4
#define NG 64
#define NCLS 10
#define BN_EPS 1e-5f

// ---------------- scratch (static device globals; no allocation) -------------
__device__ __align__(16) float g_h[NN * 256];     // GEMM output (transformed feats)
__device__ __align__(16) float g_agg[NN * 256];   // aggregation output / layer input
__device__ float g_as[NN * NHEADS];
__device__ float g_ad[NN * NHEADS];
__device__ float g_e[EE * NHEADS];
__device__ unsigned g_max[NN * NHEADS];
__device__ float g_den[NN * NHEADS];
__device__ float g_bn[2 * 256];
__device__ float g_pool[NG * HIDC];
__device__ float g_cnt[NG];

// ---------------- helpers ----------------------------------------------------
__device__ __forceinline__ unsigned ffl(float f) {
    unsigned u = __float_as_uint(f);
    return u ^ (((unsigned)((int)u >> 31)) | 0x80000000u);
}
__device__ __forceinline__ float funfl(unsigned u) {
    unsigned m = (u >> 31) ? 0x80000000u : 0xFFFFFFFFu;
    return __uint_as_float(u ^ m);
}

__global__ void zero_f_k(float* p, int n) {
    int i = blockIdx.x * blockDim.x + threadIdx.x;
    if (i < n) p[i] = 0.f;
}
__global__ void zero_u_k(unsigned* p, int n) {
    int i = blockIdx.x * blockDim.x + threadIdx.x;
    if (i < n) p[i] = 0u;
}

// ---------------- SGEMM: C[n,M] = A[n,K] @ B[K,M] ---------------------------
__global__ void sgemm_k(const float* __restrict__ A, const float* __restrict__ B,
                        float* __restrict__ C, int n, int K, int M) {
    __shared__ float sA[16][64];
    __shared__ float sB[16][64];
    int tid = threadIdx.x;
    int tx = tid & 15, ty = tid >> 4;
    int row0 = blockIdx.x * 64, col0 = blockIdx.y * 64;
    float acc[4][4] = {};
    for (int k0 = 0; k0 < K; k0 += 16) {
#pragma unroll
        for (int i = 0; i < 4; i++) {
            int e = i * 256 + tid;
            int r = e >> 4, kk = e & 15;
            sA[kk][r] = (row0 + r < n) ? A[(size_t)(row0 + r) * K + k0 + kk] : 0.f;
            int kk2 = e >> 6, c = e & 63;
            sB[kk2][c] = B[(size_t)(k0 + kk2) * M + col0 + c];
        }
        __syncthreads();
#pragma unroll
        for (int kk = 0; kk < 16; kk++) {
            float a[4], bb[4];
#pragma unroll
            for (int i = 0; i < 4; i++) a[i] = sA[kk][ty * 4 + i];
#pragma unroll
            for (int j = 0; j < 4; j++) bb[j] = sB[kk][tx * 4 + j];
#pragma unroll
            for (int i = 0; i < 4; i++)
#pragma unroll
                for (int j = 0; j < 4; j++) acc[i][j] += a[i] * bb[j];
        }
        __syncthreads();
    }
#pragma unroll
    for (int i = 0; i < 4; i++) {
        int r = row0 + ty * 4 + i;
        if (r < n) {
#pragma unroll
            for (int j = 0; j < 4; j++)
                C[(size_t)r * M + col0 + tx * 4 + j] = acc[i][j];
        }
    }
}

// ---------------- per-node attention logits ---------------------------------
__global__ void logits_k(const float* __restrict__ h, const float* __restrict__ asrc,
                         const float* __restrict__ adst, int H) {
    int idx = blockIdx.x * blockDim.x + threadIdx.x;
    if (idx >= NN * H) return;
    int node = idx / H, hh = idx - node * H;
    const float4* hv = (const float4*)(h + (size_t)node * H * HIDC + hh * HIDC);
    const float4* av = (const float4*)(asrc + hh * HIDC);
    const float4* dv = (const float4*)(adst + hh * HIDC);
    float s = 0.f, d = 0.f;
#pragma unroll
    for (int i = 0; i < HIDC / 4; i++) {
        float4 x = hv[i], a = av[i], b = dv[i];
        s += x.x * a.x + x.y * a.y + x.z * a.z + x.w * a.w;
        d += x.x * b.x + x.y * b.y + x.z * b.z + x.w * b.w;
    }
    g_as[idx] = s;
    g_ad[idx] = d;
}

// ---------------- edge: leaky-relu logit + segment max ----------------------
__global__ void edge_e_k(const int* __restrict__ src, const int* __restrict__ dst, int H) {
    int idx = blockIdx.x * blockDim.x + threadIdx.x;
    if (idx >= EE * H) return;
    int e = idx / H, hh = idx - e * H;
    int s = src[e], d = dst[e];
    float v = g_as[s * H + hh] + g_ad[d * H + hh];
    v = (v > 0.f) ? v : 0.2f * v;
    g_e[idx] = v;
    atomicMax(&g_max[d * H + hh], ffl(v));
}

// ---------------- edge: exp + segment sum -----------------------------------
__global__ void edge_exp_k(const int* __restrict__ dst, int H) {
    int idx = blockIdx.x * blockDim.x + threadIdx.x;
    if (idx >= EE * H) return;
    int e = idx / H, hh = idx - e * H;
    int d = dst[e];
    float m = funfl(g_max[d * H + hh]);
    float ex = __expf(g_e[idx] - m);
    g_e[idx] = ex;
    atomicAdd(&g_den[d * H + hh], ex);
}

// ---------------- edge: weighted scatter-aggregate (warp per edge) ----------
__global__ void edge_agg_k(const int* __restrict__ src, const int* __restrict__ dst,
                           int H, int HC) {
    int warp = (blockIdx.x * blockDim.x + threadIdx.x) >> 5;
    int lane = threadIdx.x & 31;
    if (warp >= EE) return;
    int s = src[warp], d = dst[warp];
    int nf4 = HC >> 2;
    const float4* hv = (const float4*)(g_h + (size_t)s * HC);
    float4* ov = (float4*)(g_agg + (size_t)d * HC);
    for (int i = lane; i < nf4; i += 32) {
        int hh = i >> 4;  // (i*4)/64
        float alpha = g_e[warp * H + hh] / g_den[d * H + hh];
        float4 x = hv[i];
        x.x *= alpha; x.y *= alpha; x.z *= alpha; x.w *= alpha;
        asm volatile("red.global.add.v4.f32 [%0], {%1,%2,%3,%4};"
                     :: "l"(ov + i), "f"(x.x), "f"(x.y), "f"(x.z), "f"(x.w)
                     : "memory");
    }
}

// ---------------- bias + relu (in place) + BN stats -------------------------
__global__ void brs_k(float* __restrict__ y, const float* __restrict__ b,
                      int n, int HC, int rowsPer) {
    int c = threadIdx.x;  // blockDim.x == HC
    int r0 = blockIdx.x * rowsPer;
    int r1 = min(r0 + rowsPer, n);
    float bias = b[c], s = 0.f, ss = 0.f;
    for (int r = r0; r < r1; r++) {
        float v = y[(size_t)r * HC + c] + bias;
        v = fmaxf(v, 0.f);
        y[(size_t)r * HC + c] = v;
        s += v;
        ss += v * v;
    }
    atomicAdd(&g_bn[c], s);
    atomicAdd(&g_bn[HC + c], ss);
}

// ---------------- batch norm normalize (in place) ---------------------------
__global__ void norm_k(float* __restrict__ y, const float* __restrict__ gam,
                       const float* __restrict__ bet, int n, int HC) {
    int idx = blockIdx.x * blockDim.x + threadIdx.x;
    if (idx >= n * HC) return;
    int c = idx % HC;
    float inv_n = 1.0f / (float)n;
    float mean = g_bn[c] * inv_n;
    float var = g_bn[HC + c] * inv_n - mean * mean;
    y[idx] = (y[idx] - mean) * rsqrtf(var + BN_EPS) * gam[c] + bet[c];
}

// ---------------- global mean pool ------------------------------------------
__global__ void pool_k(const float* __restrict__ h, const int* __restrict__ batch) {
    int idx = blockIdx.x * blockDim.x + threadIdx.x;
    if (idx >= NN * HIDC) return;
    int n = idx / HIDC, c = idx - n * HIDC;
    int g = batch[n];
    atomicAdd(&g_pool[g * HIDC + c], h[idx]);
    if (c == 0) atomicAdd(&g_cnt[g], 1.0f);
}

// ---------------- final FC ---------------------------------------------------
__global__ void fc_k(const float* __restrict__ fcW, const float* __restrict__ fcb,
                     float* __restrict__ out) {
    int idx = threadIdx.x;
    if (idx >= NG * NCLS) return;
    int g = idx / NCLS, c = idx - g * NCLS;
    float cnt = fmaxf(g_cnt[g], 1.0f);
    float inv = 1.0f / cnt;
    float s = fcb[c];
#pragma unroll
    for (int k = 0; k < HIDC; k++)
        s += (g_pool[g * HIDC + k] * inv) * fcW[k * NCLS + c];
    out[idx] = s;
}

// ---------------- host orchestration ----------------------------------------
static inline int ceil_div(int a, int b) { return (a + b - 1) / b; }

extern "C" void kernel_launch(void* const* d_in, const int* in_sizes, int n_in,
                              void* d_out, int out_size) {
    const float* x   = (const float*)d_in[0];
    const int* ei    = (const int*)d_in[1];
    const int* batch = (const int*)d_in[2];
    const float* W1  = (const float*)d_in[3];
    const float* as1 = (const float*)d_in[4];
    const float* ad1 = (const float*)d_in[5];
    const float* b1  = (const float*)d_in[6];
    const float* g1  = (const float*)d_in[7];
    const float* be1 = (const float*)d_in[8];
    const float* W2  = (const float*)d_in[9];
    const float* as2 = (const float*)d_in[10];
    const float* ad2 = (const float*)d_in[11];
    const float* b2  = (const float*)d_in[12];
    const float* g2  = (const float*)d_in[13];
    const float* be2 = (const float*)d_in[14];
    const float* W3  = (const float*)d_in[15];
    const float* as3 = (const float*)d_in[16];
    const float* ad3 = (const float*)d_in[17];
    const float* b3  = (const float*)d_in[18];
    const float* g3  = (const float*)d_in[19];
    const float* be3 = (const float*)d_in[20];
    const float* fcW = (const float*)d_in[21];
    const float* fcb = (const float*)d_in[22];
    const int* src = ei;
    const int* dst = ei + EE;

    float *hbuf, *aggbuf, *denbuf, *bnbuf, *poolbuf, *cntbuf;
    unsigned* maxbuf;
    cudaGetSymbolAddress((void**)&hbuf, g_h);
    cudaGetSymbolAddress((void**)&aggbuf, g_agg);
    cudaGetSymbolAddress((void**)&maxbuf, g_max);
    cudaGetSymbolAddress((void**)&denbuf, g_den);
    cudaGetSymbolAddress((void**)&bnbuf, g_bn);
    cudaGetSymbolAddress((void**)&poolbuf, g_pool);
    cudaGetSymbolAddress((void**)&cntbuf, g_cnt);

    auto run_layer = [&](const float* in, int K, const float* W, const float* asv,
                         const float* adv, const float* b, const float* gam,
                         const float* bet, int H) {
        int HC = H * HIDC;
        // 1. GEMM: in[NN,K] @ W[K,HC] -> g_h
        dim3 gg(ceil_div(NN, 64), HC / 64);
        sgemm_k<<<gg, 256>>>(in, W, hbuf, NN, K, HC);
        // 2. reset scratch (runs after GEMM consumed previous agg buffer)
        zero_f_k<<<ceil_div(NN * HC, 256), 256>>>(aggbuf, NN * HC);
        zero_u_k<<<ceil_div(NN * H, 256), 256>>>(maxbuf, NN * H);
        zero_f_k<<<ceil_div(NN * H, 256), 256>>>(denbuf, NN * H);
        zero_f_k<<<2, 256>>>(bnbuf, 2 * HC);
        // 3. per-node attention logits
        logits_k<<<ceil_div(NN * H, 256), 256>>>(hbuf, asv, adv, H);
        // 4. edge logits + segment max
        edge_e_k<<<ceil_div(EE * H, 256), 256>>>(src, dst, H);
        // 5. exp + segment sum
        edge_exp_k<<<ceil_div(EE * H, 256), 256>>>(dst, H);
        // 6. weighted scatter aggregate (warp per edge)
        edge_agg_k<<<ceil_div(EE * 32, 256), 256>>>(src, dst, H, HC);
        // 7. bias + relu + BN stats
        {
            int nBlocks = 512;
            int rowsPer = ceil_div(NN, nBlocks);
            brs_k<<<nBlocks, HC>>>(aggbuf, b, NN, HC, rowsPer);
        }
        // 8. normalize
        norm_k<<<ceil_div(NN * HC, 256), 256>>>(aggbuf, gam, bet, NN, HC);
    };

    run_layer(x,      INC, W1, as1, ad1, b1, g1, be1, NHEADS);
    run_layer(aggbuf, 256, W2, as2, ad2, b2, g2, be2, NHEADS);
    run_layer(aggbuf, 256, W3, as3, ad3, b3, g3, be3, 1);

    // global mean pool + FC
    zero_f_k<<<ceil_div(NG * HIDC, 256), 256>>>(poolbuf, NG * HIDC);
    zero_f_k<<<1, NG>>>(cntbuf, NG);
    pool_k<<<ceil_div(NN * HIDC, 256), 256>>>(aggbuf, batch);
    fc_k<<<1, 640>>>(fcW, fcb, (float*)d_out);
}

// round 2
// speedup vs baseline: 1.9870x; 1.9870x over previous
#include <cuda_runtime.h>
#include <math.h>

#define NN 50000
#define EE 800000
#define INC 128
#define HIDC 64
#define NHEADS 4
#define NG 64
#define NCLS 10
#define BN_EPS 1e-5f

// ---------------- scratch (static device globals) ---------------------------
__device__ __align__(16) float g_h[NN * 256];     // GEMM output
__device__ __align__(16) float g_agg[NN * 256];   // aggregation output / layer input
__device__ float g_as[NN * NHEADS];
__device__ float g_ad[NN * NHEADS];
__device__ int   g_rp[NN + 1];                    // CSR row ptr (by dst)
__device__ int   g_cur[NN];                       // degree counter / fill cursor
__device__ int   g_col[EE];                       // CSR: src node per slot
__device__ float g_bn[2 * 256];
__device__ float g_scl[256];
__device__ float g_sh[256];
__device__ float g_pool[NG * HIDC];
__device__ float g_cnt[NG];

static inline int ceil_div(int a, int b) { return (a + b - 1) / b; }

// ---------------- zero kernels ----------------------------------------------
__global__ void zero_f_k(float* p, int n) {
    int i = blockIdx.x * blockDim.x + threadIdx.x;
    if (i < n) p[i] = 0.f;
}
__global__ void zero_i_k(int* p, int n) {
    int i = blockIdx.x * blockDim.x + threadIdx.x;
    if (i < n) p[i] = 0;
}

// ---------------- CSR build --------------------------------------------------
__global__ void count_k(const int* __restrict__ dst) {
    int e = blockIdx.x * blockDim.x + threadIdx.x;
    if (e < EE) atomicAdd(&g_cur[dst[e]], 1);
}

#define SCAN_T 512
__global__ void scan_k() {
    __shared__ int sh[SCAN_T];
    int t = threadIdx.x;
    int chunk = (NN + SCAN_T - 1) / SCAN_T;
    int base = t * chunk;
    int s = 0;
    for (int j = 0; j < chunk; j++) {
        int idx = base + j;
        if (idx < NN) s += g_cur[idx];
    }
    sh[t] = s;
    __syncthreads();
    for (int off = 1; off < SCAN_T; off <<= 1) {
        int v = (t >= off) ? sh[t - off] : 0;
        __syncthreads();
        sh[t] += v;
        __syncthreads();
    }
    int running = sh[t] - s;  // exclusive prefix
    for (int j = 0; j < chunk; j++) {
        int idx = base + j;
        if (idx < NN) {
            int d = g_cur[idx];
            g_rp[idx] = running;
            g_cur[idx] = running;  // reset as insertion cursor
            running += d;
        }
    }
    if (t == SCAN_T - 1) g_rp[NN] = sh[SCAN_T - 1];
}

__global__ void fill_k(const int* __restrict__ src, const int* __restrict__ dst) {
    int e = blockIdx.x * blockDim.x + threadIdx.x;
    if (e >= EE) return;
    int p = atomicAdd(&g_cur[dst[e]], 1);
    g_col[p] = src[e];
}

// ---------------- SGEMM: C[n,M] = A'[n,K] @ B[K,M], A' = A*scl+sh -----------
__global__ void sgemm_k(const float* __restrict__ A, const float* __restrict__ B,
                        float* __restrict__ C, int n, int K, int M, int useBN) {
    __shared__ float sA[16][132];
    __shared__ float sB[16][64];
    int tid = threadIdx.x;
    int tx = tid & 15;   // col group (4 cols)
    int ty = tid >> 4;   // row group (8 rows)
    int row0 = blockIdx.x * 128, col0 = blockIdx.y * 64;
    float acc[8][4] = {};
    for (int k0 = 0; k0 < K; k0 += 16) {
        // load A tile 128x16 (512 float4, 2 per thread)
#pragma unroll
        for (int i = 0; i < 2; i++) {
            int f = tid * 2 + i;
            int r = f >> 2;
            int kq = (f & 3) * 4;
            float4 v = make_float4(0.f, 0.f, 0.f, 0.f);
            int gr = row0 + r;
            if (gr < n) v = *(const float4*)&A[(size_t)gr * K + k0 + kq];
            if (useBN) {
                v.x = v.x * g_scl[k0 + kq + 0] + g_sh[k0 + kq + 0];
                v.y = v.y * g_scl[k0 + kq + 1] + g_sh[k0 + kq + 1];
                v.z = v.z * g_scl[k0 + kq + 2] + g_sh[k0 + kq + 2];
                v.w = v.w * g_scl[k0 + kq + 3] + g_sh[k0 + kq + 3];
            }
            sA[kq + 0][r] = v.x;
            sA[kq + 1][r] = v.y;
            sA[kq + 2][r] = v.z;
            sA[kq + 3][r] = v.w;
        }
        // load B tile 16x64 (256 float4, 1 per thread)
        {
            int br = tid >> 4, bc = (tid & 15) * 4;
            *(float4*)&sB[br][bc] = *(const float4*)&B[(size_t)(k0 + br) * M + col0 + bc];
        }
        __syncthreads();
#pragma unroll
        for (int kk = 0; kk < 16; kk++) {
            float4 a0 = *(float4*)&sA[kk][ty * 8];
            float4 a1 = *(float4*)&sA[kk][ty * 8 + 4];
            float4 b  = *(float4*)&sB[kk][tx * 4];
            float av[8] = {a0.x, a0.y, a0.z, a0.w, a1.x, a1.y, a1.z, a1.w};
            float bv[4] = {b.x, b.y, b.z, b.w};
#pragma unroll
            for (int i = 0; i < 8; i++)
#pragma unroll
                for (int j = 0; j < 4; j++) acc[i][j] += av[i] * bv[j];
        }
        __syncthreads();
    }
#pragma unroll
    for (int i = 0; i < 8; i++) {
        int r = row0 + ty * 8 + i;
        if (r < n)
            *(float4*)&C[(size_t)r * M + col0 + tx * 4] =
                make_float4(acc[i][0], acc[i][1], acc[i][2], acc[i][3]);
    }
}

// ---------------- per-node attention logits ---------------------------------
__global__ void logits_k(const float* __restrict__ h, const float* __restrict__ asrc,
                         const float* __restrict__ adst, int H) {
    int idx = blockIdx.x * blockDim.x + threadIdx.x;
    if (idx >= NN * H) return;
    int node = idx / H, hh = idx - node * H;
    const float4* hv = (const float4*)(h + (size_t)node * H * HIDC + hh * HIDC);
    const float4* av = (const float4*)(asrc + hh * HIDC);
    const float4* dv = (const float4*)(adst + hh * HIDC);
    float s = 0.f, d = 0.f;
#pragma unroll
    for (int i = 0; i < HIDC / 4; i++) {
        float4 x = hv[i], a = av[i], b = dv[i];
        s += x.x * a.x + x.y * a.y + x.z * a.z + x.w * a.w;
        d += x.x * b.x + x.y * b.y + x.z * b.z + x.w * b.w;
    }
    g_as[idx] = s;
    g_ad[idx] = d;
}

// ---------------- gather aggregation, H=4 (warp per dst node) ---------------
// out[d] = relu( (sum_e exp(leaky(e)) * h[src]) / den + bias )
__global__ void agg4_k(const float* __restrict__ bias) {
    int warp = (blockIdx.x * blockDim.x + threadIdx.x) >> 5;
    int lane = threadIdx.x & 31;
    if (warp >= NN) return;
    int node = warp;
    float ad_h = (lane < 4) ? g_ad[node * 4 + lane] : 0.f;
    float den = 0.f;
    float4 acc0 = make_float4(0.f, 0.f, 0.f, 0.f);
    float4 acc1 = make_float4(0.f, 0.f, 0.f, 0.f);
    int beg = g_rp[node], end = g_rp[node + 1];
    int hs0 = lane >> 4;        // head of float4 idx = lane   (0 or 1)
    int hs1 = hs0 + 2;          // head of float4 idx = lane+32 (2 or 3)
    for (int j = beg; j < end; j++) {
        int s = __ldg(&g_col[j]);
        float ex = 0.f;
        if (lane < 4) {
            float v = __ldg(&g_as[s * 4 + lane]) + ad_h;
            v = (v > 0.f) ? v : 0.2f * v;
            ex = __expf(v);
            den += ex;
        }
        float exA = __shfl_sync(0xffffffffu, ex, hs0);
        float exB = __shfl_sync(0xffffffffu, ex, hs1);
        const float4* hv = (const float4*)(g_h + (size_t)s * 256);
        float4 xa = __ldg(&hv[lane]);
        float4 xb = __ldg(&hv[lane + 32]);
        acc0.x += exA * xa.x; acc0.y += exA * xa.y;
        acc0.z += exA * xa.z; acc0.w += exA * xa.w;
        acc1.x += exB * xb.x; acc1.y += exB * xb.y;
        acc1.z += exB * xb.z; acc1.w += exB * xb.w;
    }
    float denA = __shfl_sync(0xffffffffu, den, hs0);
    float denB = __shfl_sync(0xffffffffu, den, hs1);
    float invA = (denA > 0.f) ? 1.f / denA : 0.f;
    float invB = (denB > 0.f) ? 1.f / denB : 0.f;
    float4 bA = ((const float4*)bias)[lane];
    float4 bB = ((const float4*)bias)[lane + 32];
    float4 oA, oB;
    oA.x = fmaxf(acc0.x * invA + bA.x, 0.f);
    oA.y = fmaxf(acc0.y * invA + bA.y, 0.f);
    oA.z = fmaxf(acc0.z * invA + bA.z, 0.f);
    oA.w = fmaxf(acc0.w * invA + bA.w, 0.f);
    oB.x = fmaxf(acc1.x * invB + bB.x, 0.f);
    oB.y = fmaxf(acc1.y * invB + bB.y, 0.f);
    oB.z = fmaxf(acc1.z * invB + bB.z, 0.f);
    oB.w = fmaxf(acc1.w * invB + bB.w, 0.f);
    float4* ov = (float4*)(g_agg + (size_t)node * 256);
    ov[lane] = oA;
    ov[lane + 32] = oB;
}

// ---------------- gather aggregation, H=1 (warp per dst node, 16 lanes) -----
__global__ void agg1_k(const float* __restrict__ bias) {
    int warp = (blockIdx.x * blockDim.x + threadIdx.x) >> 5;
    int lane = threadIdx.x & 31;
    if (warp >= NN) return;
    int node = warp;
    float ad0 = g_ad[node];
    float den = 0.f;
    float4 acc = make_float4(0.f, 0.f, 0.f, 0.f);
    int beg = g_rp[node], end = g_rp[node + 1];
    for (int j = beg; j < end; j++) {
        int s = __ldg(&g_col[j]);
        float ex = 0.f;
        if (lane == 0) {
            float v = __ldg(&g_as[s]) + ad0;
            v = (v > 0.f) ? v : 0.2f * v;
            ex = __expf(v);
            den += ex;
        }
        ex = __shfl_sync(0xffffffffu, ex, 0);
        if (lane < 16) {
            const float4* hv = (const float4*)(g_h + (size_t)s * 64);
            float4 x = __ldg(&hv[lane]);
            acc.x += ex * x.x; acc.y += ex * x.y;
            acc.z += ex * x.z; acc.w += ex * x.w;
        }
    }
    den = __shfl_sync(0xffffffffu, den, 0);
    float inv = (den > 0.f) ? 1.f / den : 0.f;
    if (lane < 16) {
        float4 b = ((const float4*)bias)[lane];
        float4 o;
        o.x = fmaxf(acc.x * inv + b.x, 0.f);
        o.y = fmaxf(acc.y * inv + b.y, 0.f);
        o.z = fmaxf(acc.z * inv + b.z, 0.f);
        o.w = fmaxf(acc.w * inv + b.w, 0.f);
        ((float4*)(g_agg + (size_t)node * 64))[lane] = o;
    }
}

// ---------------- BN stats (read-only, per-block partials) -------------------
__global__ void stats_k(const float* __restrict__ y, int n, int HC, int rowsPer) {
    int c = threadIdx.x;  // blockDim.x == HC
    int r0 = blockIdx.x * rowsPer;
    int r1 = min(r0 + rowsPer, n);
    float s = 0.f, ss = 0.f;
    for (int r = r0; r < r1; r++) {
        float v = y[(size_t)r * HC + c];
        s += v;
        ss += v * v;
    }
    atomicAdd(&g_bn[c], s);
    atomicAdd(&g_bn[HC + c], ss);
}

// ---------------- make BN scale/shift ----------------------------------------
__global__ void mkbn_k(const float* __restrict__ gam, const float* __restrict__ bet,
                       int HC, int n) {
    int c = threadIdx.x;
    if (c >= HC) return;
    float inv_n = 1.f / (float)n;
    float mean = g_bn[c] * inv_n;
    float var = g_bn[HC + c] * inv_n - mean * mean;
    float s = rsqrtf(var + BN_EPS) * gam[c];
    g_scl[c] = s;
    g_sh[c] = bet[c] - mean * s;
}

// ---------------- pool (applies final BN inline) -----------------------------
__global__ void cnt_k(const int* __restrict__ batch) {
    int n = blockIdx.x * blockDim.x + threadIdx.x;
    if (n < NN) atomicAdd(&g_cnt[batch[n]], 1.f);
}
__global__ void pool_k(const float* __restrict__ h, const int* __restrict__ batch) {
    int idx = blockIdx.x * blockDim.x + threadIdx.x;
    if (idx >= NN * HIDC) return;
    int n = idx / HIDC, c = idx - n * HIDC;
    int g = batch[n];
    float v = h[idx] * g_scl[c] + g_sh[c];
    atomicAdd(&g_pool[g * HIDC + c], v);
}

// ---------------- final FC ---------------------------------------------------
__global__ void fc_k(const float* __restrict__ fcW, const float* __restrict__ fcb,
                     float* __restrict__ out) {
    int idx = threadIdx.x;
    if (idx >= NG * NCLS) return;
    int g = idx / NCLS, c = idx - g * NCLS;
    float cnt = fmaxf(g_cnt[g], 1.0f);
    float inv = 1.0f / cnt;
    float s = fcb[c];
#pragma unroll
    for (int k = 0; k < HIDC; k++)
        s += (g_pool[g * HIDC + k] * inv) * fcW[k * NCLS + c];
    out[idx] = s;
}

// ---------------- host orchestration ----------------------------------------
extern "C" void kernel_launch(void* const* d_in, const int* in_sizes, int n_in,
                              void* d_out, int out_size) {
    const float* x   = (const float*)d_in[0];
    const int* ei    = (const int*)d_in[1];
    const int* batch = (const int*)d_in[2];
    const float* W1  = (const float*)d_in[3];
    const float* as1 = (const float*)d_in[4];
    const float* ad1 = (const float*)d_in[5];
    const float* b1  = (const float*)d_in[6];
    const float* g1  = (const float*)d_in[7];
    const float* be1 = (const float*)d_in[8];
    const float* W2  = (const float*)d_in[9];
    const float* as2 = (const float*)d_in[10];
    const float* ad2 = (const float*)d_in[11];
    const float* b2  = (const float*)d_in[12];
    const float* g2  = (const float*)d_in[13];
    const float* be2 = (const float*)d_in[14];
    const float* W3  = (const float*)d_in[15];
    const float* as3 = (const float*)d_in[16];
    const float* ad3 = (const float*)d_in[17];
    const float* b3  = (const float*)d_in[18];
    const float* g3  = (const float*)d_in[19];
    const float* be3 = (const float*)d_in[20];
    const float* fcW = (const float*)d_in[21];
    const float* fcb = (const float*)d_in[22];
    const int* src = ei;
    const int* dst = ei + EE;

    float *hbuf, *aggbuf, *bnbuf, *poolbuf, *cntbuf;
    int* curbuf;
    cudaGetSymbolAddress((void**)&hbuf, g_h);
    cudaGetSymbolAddress((void**)&aggbuf, g_agg);
    cudaGetSymbolAddress((void**)&bnbuf, g_bn);
    cudaGetSymbolAddress((void**)&poolbuf, g_pool);
    cudaGetSymbolAddress((void**)&cntbuf, g_cnt);
    cudaGetSymbolAddress((void**)&curbuf, g_cur);

    // ---- build CSR (dst -> list of src) once ----
    zero_i_k<<<ceil_div(NN, 256), 256>>>(curbuf, NN);
    count_k<<<ceil_div(EE, 256), 256>>>(dst);
    scan_k<<<1, SCAN_T>>>();
    fill_k<<<ceil_div(EE, 256), 256>>>(src, dst);

    auto run_layer = [&](const float* in, int K, const float* W, const float* asv,
                         const float* adv, const float* b, const float* gam,
                         const float* bet, int H, int useBN) {
        int HC = H * HIDC;
        dim3 gg(ceil_div(NN, 128), HC / 64);
        sgemm_k<<<gg, 256>>>(in, W, hbuf, NN, K, HC, useBN);
        logits_k<<<ceil_div(NN * H, 256), 256>>>(hbuf, asv, adv, H);
        if (H == 4)
            agg4_k<<<ceil_div(NN * 32, 256), 256>>>(b);
        else
            agg1_k<<<ceil_div(NN * 32, 256), 256>>>(b);
        zero_f_k<<<2, 256>>>(bnbuf, 2 * HC);
        stats_k<<<512, HC>>>(aggbuf, NN, HC, ceil_div(NN, 512));
        mkbn_k<<<1, 256>>>(gam, bet, HC, NN);
    };

    run_layer(x,      INC, W1, as1, ad1, b1, g1, be1, NHEADS, 0);
    run_layer(aggbuf, 256, W2, as2, ad2, b2, g2, be2, NHEADS, 1);
    run_layer(aggbuf, 256, W3, as3, ad3, b3, g3, be3, 1, 1);

    // ---- global mean pool (applies layer-3 BN inline) + FC ----
    zero_f_k<<<ceil_div(NG * HIDC, 256), 256>>>(poolbuf, NG * HIDC);
    zero_f_k<<<1, NG>>>(cntbuf, NG);
    cnt_k<<<ceil_div(NN, 256), 256>>>(batch);
    pool_k<<<ceil_div(NN * HIDC, 256), 256>>>(aggbuf, batch);
    fc_k<<<1, 640>>>(fcW, fcb, (float*)d_out);
}

// round 3
// speedup vs baseline: 2.6541x; 1.3358x over previous
#include <cuda_runtime.h>
#include <math.h>

#define NN 50000
#define EE 800000
#define INC 128
#define HIDC 64
#define NHEADS 4
#define NG 64
#define NCLS 10
#define BN_EPS 1e-5f

typedef unsigned int uint;

// ---------------- scratch (static device globals) ---------------------------
__device__ __align__(16) float g_h[NN * 256];     // GEMM output
__device__ __align__(16) float g_agg[NN * 256];   // aggregation output / layer input
__device__ float g_as[NN * NHEADS];
__device__ float g_ad[NN * NHEADS];
__device__ int   g_rp[NN + 1];                    // CSR row ptr (by dst)
__device__ int   g_cur[NN];                       // degree counter / fill cursor
__device__ int   g_col[EE];                       // CSR: src node per slot
__device__ float g_bn[2 * 256];
__device__ float g_scl[256];
__device__ float g_sh[256];
__device__ float g_pool[NG * HIDC];
__device__ float g_cnt[NG];

static inline int ceil_div(int a, int b) { return (a + b - 1) / b; }

// ---------------- zero kernels ----------------------------------------------
__global__ void zero_f_k(float* p, int n) {
    int i = blockIdx.x * blockDim.x + threadIdx.x;
    if (i < n) p[i] = 0.f;
}
__global__ void zero_i_k(int* p, int n) {
    int i = blockIdx.x * blockDim.x + threadIdx.x;
    if (i < n) p[i] = 0;
}

// ---------------- CSR build --------------------------------------------------
__global__ void count_k(const int* __restrict__ dst) {
    int e = blockIdx.x * blockDim.x + threadIdx.x;
    if (e < EE) atomicAdd(&g_cur[dst[e]], 1);
}

#define SCAN_T 512
__global__ void scan_k() {
    __shared__ int sh[SCAN_T];
    int t = threadIdx.x;
    int chunk = (NN + SCAN_T - 1) / SCAN_T;
    int base = t * chunk;
    int s = 0;
    for (int j = 0; j < chunk; j++) {
        int idx = base + j;
        if (idx < NN) s += g_cur[idx];
    }
    sh[t] = s;
    __syncthreads();
    for (int off = 1; off < SCAN_T; off <<= 1) {
        int v = (t >= off) ? sh[t - off] : 0;
        __syncthreads();
        sh[t] += v;
        __syncthreads();
    }
    int running = sh[t] - s;  // exclusive prefix
    for (int j = 0; j < chunk; j++) {
        int idx = base + j;
        if (idx < NN) {
            int d = g_cur[idx];
            g_rp[idx] = running;
            g_cur[idx] = running;  // reset as insertion cursor
            running += d;
        }
    }
    if (t == SCAN_T - 1) g_rp[NN] = sh[SCAN_T - 1];
}

__global__ void fill_k(const int* __restrict__ src, const int* __restrict__ dst) {
    int e = blockIdx.x * blockDim.x + threadIdx.x;
    if (e >= EE) return;
    int p = atomicAdd(&g_cur[dst[e]], 1);
    g_col[p] = src[e];
}

// ---------------- tf32 tensor-core GEMM -------------------------------------
// C[n,M] = A'[n,K] @ B[K,M],  A' = A*scl+sh (folded prev-layer BN)
#define BM 128
#define BN 64
#define BK 32
#define SAS (BK + 4)   // 36: A smem row stride (conflict-free frag loads)
#define SBS (BN + 8)   // 72: B smem row stride (conflict-free frag loads)

__device__ __forceinline__ uint f2tf32(float x) {
    uint r;
    asm("cvt.rna.tf32.f32 %0, %1;" : "=r"(r) : "f"(x));
    return r;
}

__global__ void __launch_bounds__(256) tgemm_k(const float* __restrict__ A,
                                               const float* __restrict__ B,
                                               float* __restrict__ C,
                                               int n, int K, int M, int useBN) {
    __shared__ uint sA[BM][SAS];
    __shared__ uint sB[BK][SBS];
    int tid = threadIdx.x;
    int lane = tid & 31;
    int wid = tid >> 5;
    int warpM = wid >> 1, warpN = wid & 1;     // 4x2 warp grid -> 32x32 per warp
    int gid = lane >> 2, tq = lane & 3;
    int row0 = blockIdx.x * BM, col0 = blockIdx.y * BN;

    // A load mapping: idx = i*256+tid -> r = i*32 + (tid>>3), q4 = (tid&7)*4
    int a_r = tid >> 3, a_q4 = (tid & 7) * 4;
    // B load mapping: idx = i*256+tid -> kr = i*16 + (tid>>4), nc4 = (tid&15)*4
    int b_kr = tid >> 4, b_nc4 = (tid & 15) * 4;

    float4 pa[4];
    float4 pb[2];
    float scl0 = 1.f, scl1 = 1.f, scl2 = 1.f, scl3 = 1.f;
    float sh0 = 0.f, sh1 = 0.f, sh2 = 0.f, sh3 = 0.f;

    auto loadTiles = [&](int k0) {
        if (useBN) {
            scl0 = g_scl[k0 + a_q4 + 0]; sh0 = g_sh[k0 + a_q4 + 0];
            scl1 = g_scl[k0 + a_q4 + 1]; sh1 = g_sh[k0 + a_q4 + 1];
            scl2 = g_scl[k0 + a_q4 + 2]; sh2 = g_sh[k0 + a_q4 + 2];
            scl3 = g_scl[k0 + a_q4 + 3]; sh3 = g_sh[k0 + a_q4 + 3];
        }
#pragma unroll
        for (int i = 0; i < 4; i++) {
            int gr = row0 + i * 32 + a_r;
            float4 v = make_float4(0.f, 0.f, 0.f, 0.f);
            if (gr < n) v = *(const float4*)&A[(size_t)gr * K + k0 + a_q4];
            if (useBN) {
                v.x = v.x * scl0 + sh0;
                v.y = v.y * scl1 + sh1;
                v.z = v.z * scl2 + sh2;
                v.w = v.w * scl3 + sh3;
            }
            pa[i] = v;
        }
#pragma unroll
        for (int i = 0; i < 2; i++) {
            int kr = k0 + i * 16 + b_kr;
            pb[i] = *(const float4*)&B[(size_t)kr * M + col0 + b_nc4];
        }
    };
    auto storeTiles = [&]() {
#pragma unroll
        for (int i = 0; i < 4; i++) {
            uint4 u;
            u.x = f2tf32(pa[i].x); u.y = f2tf32(pa[i].y);
            u.z = f2tf32(pa[i].z); u.w = f2tf32(pa[i].w);
            *(uint4*)&sA[i * 32 + a_r][a_q4] = u;
        }
#pragma unroll
        for (int i = 0; i < 2; i++) {
            uint4 u;
            u.x = f2tf32(pb[i].x); u.y = f2tf32(pb[i].y);
            u.z = f2tf32(pb[i].z); u.w = f2tf32(pb[i].w);
            *(uint4*)&sB[i * 16 + b_kr][b_nc4] = u;
        }
    };

    float c[2][4][4];
#pragma unroll
    for (int mt = 0; mt < 2; mt++)
#pragma unroll
        for (int nt = 0; nt < 4; nt++)
#pragma unroll
            for (int j = 0; j < 4; j++) c[mt][nt][j] = 0.f;

    int nk = K / BK;
    loadTiles(0);
    for (int it = 0; it < nk; it++) {
        storeTiles();
        __syncthreads();
        if (it + 1 < nk) loadTiles((it + 1) * BK);
#pragma unroll
        for (int ks = 0; ks < 4; ks++) {
            int k = ks * 8;
            uint a[2][4], b[4][2];
#pragma unroll
            for (int mt = 0; mt < 2; mt++) {
                int m = warpM * 32 + mt * 16;
                a[mt][0] = sA[m + gid][k + tq];
                a[mt][1] = sA[m + gid + 8][k + tq];
                a[mt][2] = sA[m + gid][k + tq + 4];
                a[mt][3] = sA[m + gid + 8][k + tq + 4];
            }
#pragma unroll
            for (int nt = 0; nt < 4; nt++) {
                int nb = warpN * 32 + nt * 8;
                b[nt][0] = sB[k + tq][nb + gid];
                b[nt][1] = sB[k + tq + 4][nb + gid];
            }
#pragma unroll
            for (int mt = 0; mt < 2; mt++)
#pragma unroll
                for (int nt = 0; nt < 4; nt++) {
                    asm volatile(
                        "mma.sync.aligned.m16n8k8.row.col.f32.tf32.tf32.f32 "
                        "{%0,%1,%2,%3}, {%4,%5,%6,%7}, {%8,%9}, {%0,%1,%2,%3};"
                        : "+f"(c[mt][nt][0]), "+f"(c[mt][nt][1]),
                          "+f"(c[mt][nt][2]), "+f"(c[mt][nt][3])
                        : "r"(a[mt][0]), "r"(a[mt][1]), "r"(a[mt][2]), "r"(a[mt][3]),
                          "r"(b[nt][0]), "r"(b[nt][1]));
                }
        }
        __syncthreads();
    }

    // epilogue
#pragma unroll
    for (int mt = 0; mt < 2; mt++) {
        int r0 = row0 + warpM * 32 + mt * 16 + gid;
        int r1 = r0 + 8;
#pragma unroll
        for (int nt = 0; nt < 4; nt++) {
            int cc = col0 + warpN * 32 + nt * 8 + tq * 2;
            if (r0 < n) *(float2*)&C[(size_t)r0 * M + cc] =
                make_float2(c[mt][nt][0], c[mt][nt][1]);
            if (r1 < n) *(float2*)&C[(size_t)r1 * M + cc] =
                make_float2(c[mt][nt][2], c[mt][nt][3]);
        }
    }
}

// ---------------- per-node attention logits ---------------------------------
__global__ void logits_k(const float* __restrict__ h, const float* __restrict__ asrc,
                         const float* __restrict__ adst, int H) {
    int idx = blockIdx.x * blockDim.x + threadIdx.x;
    if (idx >= NN * H) return;
    int node = idx / H, hh = idx - node * H;
    const float4* hv = (const float4*)(h + (size_t)node * H * HIDC + hh * HIDC);
    const float4* av = (const float4*)(asrc + hh * HIDC);
    const float4* dv = (const float4*)(adst + hh * HIDC);
    float s = 0.f, d = 0.f;
#pragma unroll
    for (int i = 0; i < HIDC / 4; i++) {
        float4 x = hv[i], a = av[i], b = dv[i];
        s += x.x * a.x + x.y * a.y + x.z * a.z + x.w * a.w;
        d += x.x * b.x + x.y * b.y + x.z * b.z + x.w * b.w;
    }
    g_as[idx] = s;
    g_ad[idx] = d;
}

// ---------------- gather aggregation, H=4 (warp per dst node) ---------------
__global__ void agg4_k(const float* __restrict__ bias) {
    int warp = (blockIdx.x * blockDim.x + threadIdx.x) >> 5;
    int lane = threadIdx.x & 31;
    if (warp >= NN) return;
    int node = warp;
    float ad_h = (lane < 4) ? g_ad[node * 4 + lane] : 0.f;
    float den = 0.f;
    float4 acc0 = make_float4(0.f, 0.f, 0.f, 0.f);
    float4 acc1 = make_float4(0.f, 0.f, 0.f, 0.f);
    int beg = g_rp[node], end = g_rp[node + 1];
    int hs0 = lane >> 4;
    int hs1 = hs0 + 2;
    int j = beg;
    // unrolled by 2 for MLP
    for (; j + 1 < end; j += 2) {
        int s0 = __ldg(&g_col[j]);
        int s1 = __ldg(&g_col[j + 1]);
        float e0 = 0.f, e1 = 0.f;
        if (lane < 4) {
            float v0 = __ldg(&g_as[s0 * 4 + lane]) + ad_h;
            float v1 = __ldg(&g_as[s1 * 4 + lane]) + ad_h;
            v0 = (v0 > 0.f) ? v0 : 0.2f * v0;
            v1 = (v1 > 0.f) ? v1 : 0.2f * v1;
            e0 = __expf(v0);
            e1 = __expf(v1);
            den += e0 + e1;
        }
        const float4* h0 = (const float4*)(g_h + (size_t)s0 * 256);
        const float4* h1 = (const float4*)(g_h + (size_t)s1 * 256);
        float4 xa0 = __ldg(&h0[lane]);
        float4 xb0 = __ldg(&h0[lane + 32]);
        float4 xa1 = __ldg(&h1[lane]);
        float4 xb1 = __ldg(&h1[lane + 32]);
        float eA0 = __shfl_sync(0xffffffffu, e0, hs0);
        float eB0 = __shfl_sync(0xffffffffu, e0, hs1);
        float eA1 = __shfl_sync(0xffffffffu, e1, hs0);
        float eB1 = __shfl_sync(0xffffffffu, e1, hs1);
        acc0.x += eA0 * xa0.x + eA1 * xa1.x;
        acc0.y += eA0 * xa0.y + eA1 * xa1.y;
        acc0.z += eA0 * xa0.z + eA1 * xa1.z;
        acc0.w += eA0 * xa0.w + eA1 * xa1.w;
        acc1.x += eB0 * xb0.x + eB1 * xb1.x;
        acc1.y += eB0 * xb0.y + eB1 * xb1.y;
        acc1.z += eB0 * xb0.z + eB1 * xb1.z;
        acc1.w += eB0 * xb0.w + eB1 * xb1.w;
    }
    if (j < end) {
        int s0 = __ldg(&g_col[j]);
        float e0 = 0.f;
        if (lane < 4) {
            float v0 = __ldg(&g_as[s0 * 4 + lane]) + ad_h;
            v0 = (v0 > 0.f) ? v0 : 0.2f * v0;
            e0 = __expf(v0);
            den += e0;
        }
        const float4* h0 = (const float4*)(g_h + (size_t)s0 * 256);
        float4 xa0 = __ldg(&h0[lane]);
        float4 xb0 = __ldg(&h0[lane + 32]);
        float eA0 = __shfl_sync(0xffffffffu, e0, hs0);
        float eB0 = __shfl_sync(0xffffffffu, e0, hs1);
        acc0.x += eA0 * xa0.x; acc0.y += eA0 * xa0.y;
        acc0.z += eA0 * xa0.z; acc0.w += eA0 * xa0.w;
        acc1.x += eB0 * xb0.x; acc1.y += eB0 * xb0.y;
        acc1.z += eB0 * xb0.z; acc1.w += eB0 * xb0.w;
    }
    float denA = __shfl_sync(0xffffffffu, den, hs0);
    float denB = __shfl_sync(0xffffffffu, den, hs1);
    float invA = (denA > 0.f) ? 1.f / denA : 0.f;
    float invB = (denB > 0.f) ? 1.f / denB : 0.f;
    float4 bA = ((const float4*)bias)[lane];
    float4 bB = ((const float4*)bias)[lane + 32];
    float4 oA, oB;
    oA.x = fmaxf(acc0.x * invA + bA.x, 0.f);
    oA.y = fmaxf(acc0.y * invA + bA.y, 0.f);
    oA.z = fmaxf(acc0.z * invA + bA.z, 0.f);
    oA.w = fmaxf(acc0.w * invA + bA.w, 0.f);
    oB.x = fmaxf(acc1.x * invB + bB.x, 0.f);
    oB.y = fmaxf(acc1.y * invB + bB.y, 0.f);
    oB.z = fmaxf(acc1.z * invB + bB.z, 0.f);
    oB.w = fmaxf(acc1.w * invB + bB.w, 0.f);
    float4* ov = (float4*)(g_agg + (size_t)node * 256);
    ov[lane] = oA;
    ov[lane + 32] = oB;
}

// ---------------- gather aggregation, H=1 -----------------------------------
__global__ void agg1_k(const float* __restrict__ bias) {
    int warp = (blockIdx.x * blockDim.x + threadIdx.x) >> 5;
    int lane = threadIdx.x & 31;
    if (warp >= NN) return;
    int node = warp;
    float ad0 = g_ad[node];
    float den = 0.f;
    float4 acc = make_float4(0.f, 0.f, 0.f, 0.f);
    int beg = g_rp[node], end = g_rp[node + 1];
    int j = beg;
    for (; j + 1 < end; j += 2) {
        int s0 = __ldg(&g_col[j]);
        int s1 = __ldg(&g_col[j + 1]);
        float e0 = 0.f, e1 = 0.f;
        if (lane == 0) {
            float v0 = __ldg(&g_as[s0]) + ad0;
            float v1 = __ldg(&g_as[s1]) + ad0;
            v0 = (v0 > 0.f) ? v0 : 0.2f * v0;
            v1 = (v1 > 0.f) ? v1 : 0.2f * v1;
            e0 = __expf(v0);
            e1 = __expf(v1);
            den += e0 + e1;
        }
        e0 = __shfl_sync(0xffffffffu, e0, 0);
        e1 = __shfl_sync(0xffffffffu, e1, 0);
        if (lane < 16) {
            float4 x0 = __ldg(&((const float4*)(g_h + (size_t)s0 * 64))[lane]);
            float4 x1 = __ldg(&((const float4*)(g_h + (size_t)s1 * 64))[lane]);
            acc.x += e0 * x0.x + e1 * x1.x;
            acc.y += e0 * x0.y + e1 * x1.y;
            acc.z += e0 * x0.z + e1 * x1.z;
            acc.w += e0 * x0.w + e1 * x1.w;
        }
    }
    if (j < end) {
        int s0 = __ldg(&g_col[j]);
        float e0 = 0.f;
        if (lane == 0) {
            float v0 = __ldg(&g_as[s0]) + ad0;
            v0 = (v0 > 0.f) ? v0 : 0.2f * v0;
            e0 = __expf(v0);
            den += e0;
        }
        e0 = __shfl_sync(0xffffffffu, e0, 0);
        if (lane < 16) {
            float4 x0 = __ldg(&((const float4*)(g_h + (size_t)s0 * 64))[lane]);
            acc.x += e0 * x0.x; acc.y += e0 * x0.y;
            acc.z += e0 * x0.z; acc.w += e0 * x0.w;
        }
    }
    den = __shfl_sync(0xffffffffu, den, 0);
    float inv = (den > 0.f) ? 1.f / den : 0.f;
    if (lane < 16) {
        float4 b = ((const float4*)bias)[lane];
        float4 o;
        o.x = fmaxf(acc.x * inv + b.x, 0.f);
        o.y = fmaxf(acc.y * inv + b.y, 0.f);
        o.z = fmaxf(acc.z * inv + b.z, 0.f);
        o.w = fmaxf(acc.w * inv + b.w, 0.f);
        ((float4*)(g_agg + (size_t)node * 64))[lane] = o;
    }
}

// ---------------- BN stats ----------------------------------------------------
__global__ void stats_k(const float* __restrict__ y, int n, int HC, int rowsPer) {
    int c = threadIdx.x;
    int r0 = blockIdx.x * rowsPer;
    int r1 = min(r0 + rowsPer, n);
    float s = 0.f, ss = 0.f;
    for (int r = r0; r < r1; r++) {
        float v = y[(size_t)r * HC + c];
        s += v;
        ss += v * v;
    }
    atomicAdd(&g_bn[c], s);
    atomicAdd(&g_bn[HC + c], ss);
}

__global__ void mkbn_k(const float* __restrict__ gam, const float* __restrict__ bet,
                       int HC, int n) {
    int c = threadIdx.x;
    if (c >= HC) return;
    float inv_n = 1.f / (float)n;
    float mean = g_bn[c] * inv_n;
    float var = g_bn[HC + c] * inv_n - mean * mean;
    float s = rsqrtf(var + BN_EPS) * gam[c];
    g_scl[c] = s;
    g_sh[c] = bet[c] - mean * s;
}

// ---------------- pool + FC ---------------------------------------------------
__global__ void cnt_k(const int* __restrict__ batch) {
    int n = blockIdx.x * blockDim.x + threadIdx.x;
    if (n < NN) atomicAdd(&g_cnt[batch[n]], 1.f);
}
__global__ void pool_k(const float* __restrict__ h, const int* __restrict__ batch) {
    int idx = blockIdx.x * blockDim.x + threadIdx.x;
    if (idx >= NN * HIDC) return;
    int n = idx / HIDC, c = idx - n * HIDC;
    int g = batch[n];
    float v = h[idx] * g_scl[c] + g_sh[c];
    atomicAdd(&g_pool[g * HIDC + c], v);
}
__global__ void fc_k(const float* __restrict__ fcW, const float* __restrict__ fcb,
                     float* __restrict__ out) {
    int idx = threadIdx.x;
    if (idx >= NG * NCLS) return;
    int g = idx / NCLS, c = idx - g * NCLS;
    float cnt = fmaxf(g_cnt[g], 1.0f);
    float inv = 1.0f / cnt;
    float s = fcb[c];
#pragma unroll
    for (int k = 0; k < HIDC; k++)
        s += (g_pool[g * HIDC + k] * inv) * fcW[k * NCLS + c];
    out[idx] = s;
}

// ---------------- host orchestration ----------------------------------------
extern "C" void kernel_launch(void* const* d_in, const int* in_sizes, int n_in,
                              void* d_out, int out_size) {
    const float* x   = (const float*)d_in[0];
    const int* ei    = (const int*)d_in[1];
    const int* batch = (const int*)d_in[2];
    const float* W1  = (const float*)d_in[3];
    const float* as1 = (const float*)d_in[4];
    const float* ad1 = (const float*)d_in[5];
    const float* b1  = (const float*)d_in[6];
    const float* g1  = (const float*)d_in[7];
    const float* be1 = (const float*)d_in[8];
    const float* W2  = (const float*)d_in[9];
    const float* as2 = (const float*)d_in[10];
    const float* ad2 = (const float*)d_in[11];
    const float* b2  = (const float*)d_in[12];
    const float* g2  = (const float*)d_in[13];
    const float* be2 = (const float*)d_in[14];
    const float* W3  = (const float*)d_in[15];
    const float* as3 = (const float*)d_in[16];
    const float* ad3 = (const float*)d_in[17];
    const float* b3  = (const float*)d_in[18];
    const float* g3  = (const float*)d_in[19];
    const float* be3 = (const float*)d_in[20];
    const float* fcW = (const float*)d_in[21];
    const float* fcb = (const float*)d_in[22];
    const int* src = ei;
    const int* dst = ei + EE;

    float *hbuf, *aggbuf, *bnbuf, *poolbuf, *cntbuf;
    int* curbuf;
    cudaGetSymbolAddress((void**)&hbuf, g_h);
    cudaGetSymbolAddress((void**)&aggbuf, g_agg);
    cudaGetSymbolAddress((void**)&bnbuf, g_bn);
    cudaGetSymbolAddress((void**)&poolbuf, g_pool);
    cudaGetSymbolAddress((void**)&cntbuf, g_cnt);
    cudaGetSymbolAddress((void**)&curbuf, g_cur);

    // ---- build CSR (dst -> list of src) ----
    zero_i_k<<<ceil_div(NN, 256), 256>>>(curbuf, NN);
    count_k<<<ceil_div(EE, 256), 256>>>(dst);
    scan_k<<<1, SCAN_T>>>();
    fill_k<<<ceil_div(EE, 256), 256>>>(src, dst);

    auto run_layer = [&](const float* in, int K, const float* W, const float* asv,
                         const float* adv, const float* b, const float* gam,
                         const float* bet, int H, int useBN) {
        int HC = H * HIDC;
        dim3 gg(ceil_div(NN, BM), HC / BN);
        tgemm_k<<<gg, 256>>>(in, W, hbuf, NN, K, HC, useBN);
        logits_k<<<ceil_div(NN * H, 256), 256>>>(hbuf, asv, adv, H);
        if (H == 4)
            agg4_k<<<ceil_div(NN * 32, 256), 256>>>(b);
        else
            agg1_k<<<ceil_div(NN * 32, 256), 256>>>(b);
        zero_f_k<<<2, 256>>>(bnbuf, 2 * HC);
        stats_k<<<512, HC>>>(aggbuf, NN, HC, ceil_div(NN, 512));
        mkbn_k<<<1, 256>>>(gam, bet, HC, NN);
    };

    run_layer(x,      INC, W1, as1, ad1, b1, g1, be1, NHEADS, 0);
    run_layer(aggbuf, 256, W2, as2, ad2, b2, g2, be2, NHEADS, 1);
    run_layer(aggbuf, 256, W3, as3, ad3, b3, g3, be3, 1, 1);

    // ---- global mean pool (applies layer-3 BN inline) + FC ----
    zero_f_k<<<ceil_div(NG * HIDC, 256), 256>>>(poolbuf, NG * HIDC);
    zero_f_k<<<1, NG>>>(cntbuf, NG);
    cnt_k<<<ceil_div(NN, 256), 256>>>(batch);
    pool_k<<<ceil_div(NN * HIDC, 256), 256>>>(aggbuf, batch);
    fc_k<<<1, 640>>>(fcW, fcb, (float*)d_out);
}